// round 7
// baseline (speedup 1.0000x reference)
#include <cuda_runtime.h>
#include <cuda_fp16.h>
#include <math.h>
#include <stdint.h>

// GraphAttentionLayer  N=8192, FIN=128, F=64  (sm_100-safe: mma.sync fp16 HMMA)
//
//  w_ij = adj ? exp(leaky_relu(s1_i + s2_j)) : 0
//       = adj ? ( (u_i*v_j >= 1) ? u_i*v_j : u5_i*v5_j ) : 0
//  out_i = elu( (sum_j w_ij h_j) / (sum_j w_ij) )
//
// fp16 single-product GEMM (P fp16 x H fp16, fp32 accum). Error budget:
// per-term fp16 rounding (~3e-4 rms) cancels by ~1/sqrt(deg) relative to the
// output scale -> aggregate rel_err ~4e-4 < 1e-3.

constexpr int N_NODES = 8192;
constexpr int FIN = 128;
constexpr int F = 64;

__device__ float g_u[N_NODES], g_u5[N_NODES], g_v[N_NODES], g_v5[N_NODES];
__device__ __half g_hT[F][N_NODES];          // h transposed, fp16
__device__ float g_num[2][N_NODES][F];
__device__ float g_zp[2][N_NODES];

__device__ __forceinline__ uint32_t smem_u32(const void* p) {
    uint32_t a;
    asm("{ .reg .u64 t; cvta.to.shared.u64 t, %1; cvt.u32.u64 %0, t; }" : "=r"(a) : "l"(p));
    return a;
}
__device__ __forceinline__ uint32_t swz(uint32_t o) { return o ^ ((o >> 3) & 0x70); }

__device__ __forceinline__ void cp_async16(uint32_t dst, const void* src) {
    asm volatile("cp.async.cg.shared.global [%0], [%1], 16;" :: "r"(dst), "l"(src) : "memory");
}
__device__ __forceinline__ void cp_commit() {
    asm volatile("cp.async.commit_group;" ::: "memory");
}
__device__ __forceinline__ void cp_wait_all() {
    asm volatile("cp.async.wait_group 0;" ::: "memory");
}
__device__ __forceinline__ void ldsm_x4(uint32_t* r, uint32_t addr) {
    asm volatile("ldmatrix.sync.aligned.m8n8.x4.shared.b16 {%0,%1,%2,%3}, [%4];"
                 : "=r"(r[0]), "=r"(r[1]), "=r"(r[2]), "=r"(r[3]) : "r"(addr));
}
__device__ __forceinline__ void mma16816(float* d, const uint32_t* a, const uint32_t* b) {
    asm volatile(
        "mma.sync.aligned.m16n8k16.row.col.f32.f16.f16.f32 "
        "{%0,%1,%2,%3}, {%4,%5,%6,%7}, {%8,%9}, {%0,%1,%2,%3};"
        : "+f"(d[0]), "+f"(d[1]), "+f"(d[2]), "+f"(d[3])
        : "r"(a[0]), "r"(a[1]), "r"(a[2]), "r"(a[3]), "r"(b[0]), "r"(b[1]));
}
__device__ __forceinline__ uint32_t cvt_f16x2(float hi_val, float lo_val) {
    uint32_t d;
    asm("cvt.rn.f16x2.f32 %0, %1, %2;" : "=r"(d) : "f"(hi_val), "f"(lo_val));
    return d;
}

// ---------------------------------------------------------------------------
// Kernel 1: projection. 256 blocks x 256 threads, 32 rows each.
// ---------------------------------------------------------------------------
constexpr int PROJ_PAD = 132;
constexpr int PR = 32;   // rows per block
constexpr int SM_PROJ = PR * PROJ_PAD * 4 + FIN * F * 4 + 2 * FIN * 4;  // ~50 KB

__global__ __launch_bounds__(256, 2) void k_proj(const float* __restrict__ inp,
                                                 const float* __restrict__ W,
                                                 const float* __restrict__ a) {
    extern __shared__ char sm[];
    float* sIn = (float*)sm;                              // [32][132]
    float* sW  = (float*)(sm + PR * PROJ_PAD * 4);        // [128][64]
    float* sA  = sW + FIN * F;                            // [128]

    const int t = threadIdx.x;
    const int i0 = blockIdx.x * PR;

    {   // stage inp rows: 32 x 128 fp32 = 1024 float4
        const float4* src = (const float4*)(inp + (size_t)i0 * FIN);
#pragma unroll
        for (int r = 0; r < 4; r++) {
            int idx = t + r * 256;
            int row = idx >> 5, col = idx & 31;
            *(float4*)(sIn + row * PROJ_PAD + col * 4) = src[idx];
        }
    }
    {   // stage W: 2048 float4
        const float4* src = (const float4*)W;
        float4* dst = (float4*)sW;
#pragma unroll
        for (int r = 0; r < 8; r++) dst[t + r * 256] = src[t + r * 256];
    }
    if (t < 128) sA[t] = a[t];
    __syncthreads();

    const int tc = t & 15, tr = t >> 4;
    const int f0 = tc * 4, r0 = tr * 2;

    float acc[2][4] = {};
#pragma unroll 4
    for (int k = 0; k < FIN; k++) {
        float4 w4 = *(const float4*)(sW + k * F + f0);
#pragma unroll
        for (int rr = 0; rr < 2; rr++) {
            float x = sIn[(r0 + rr) * PROJ_PAD + k];
            acc[rr][0] = fmaf(x, w4.x, acc[rr][0]);
            acc[rr][1] = fmaf(x, w4.y, acc[rr][1]);
            acc[rr][2] = fmaf(x, w4.z, acc[rr][2]);
            acc[rr][3] = fmaf(x, w4.w, acc[rr][3]);
        }
    }

    float p1[2], p2[2];
#pragma unroll
    for (int rr = 0; rr < 2; rr++) {
        p1[rr] = acc[rr][0] * sA[f0] + acc[rr][1] * sA[f0 + 1] +
                 acc[rr][2] * sA[f0 + 2] + acc[rr][3] * sA[f0 + 3];
        p2[rr] = acc[rr][0] * sA[64 + f0] + acc[rr][1] * sA[64 + f0 + 1] +
                 acc[rr][2] * sA[64 + f0 + 2] + acc[rr][3] * sA[64 + f0 + 3];
#pragma unroll
        for (int m = 1; m < 16; m <<= 1) {
            p1[rr] += __shfl_xor_sync(0xffffffffu, p1[rr], m);
            p2[rr] += __shfl_xor_sync(0xffffffffu, p2[rr], m);
        }
    }
    if (tc == 0) {
#pragma unroll
        for (int rr = 0; rr < 2; rr++) {
            int i = i0 + r0 + rr;
            float s1 = p1[rr], s2 = p2[rr];
            g_u[i]  = expf(s1);
            g_u5[i] = expf(0.2f * s1);
            g_v[i]  = expf(s2);
            g_v5[i] = expf(0.2f * s2);
        }
    }

    __syncthreads();
    __half* sT = (__half*)sm;                 // [64 f][32 rows] fp16 (4 KB, reuses sIn)
#pragma unroll
    for (int rr = 0; rr < 2; rr++)
#pragma unroll
        for (int c = 0; c < 4; c++)
            sT[(f0 + c) * PR + (r0 + rr)] = __float2half_rn(acc[rr][c]);
    __syncthreads();
    // STG: 64 f x 32 rows x 2B = 4KB = 256 16B chunks, 1 per thread
    {
        int f = t >> 2, col = t & 3;
        *(uint4*)((char*)&g_hT[f][i0] + col * 16) = ((const uint4*)sT)[t];
    }
}

// ---------------------------------------------------------------------------
// Kernel 2: fused masked-weight + fp16 HMMA GEMM. 128 blocks x 256 threads.
// ---------------------------------------------------------------------------
constexpr int ADJ_PITCH = 272;                   // bytes per adj tile row (64 ints + 16B pad)
constexpr int SM_P   = 1024;                     // 128x64 fp16, SW128 (16 KB)
constexpr int SM_H   = SM_P + 16384;             // 2 bufs x 64x64 fp16 (8 KB each)
constexpr int SM_ADJ = SM_H + 16384;             // 2 bufs x 128 x 272B (~68 KB)
constexpr int SM_V   = SM_ADJ + 2 * 128 * ADJ_PITCH;
constexpr int SM_V5  = SM_V + 16384;
constexpr int SM_ATTN = SM_V5 + 16384;           // ~134 KB

__global__ __launch_bounds__(256, 1) void k_attn(const int* __restrict__ adj) {
    extern __shared__ char sm[];
    const uint32_t smb = smem_u32(sm);
    const int t = threadIdx.x;
    const int lane = t & 31;
    const int wid = t >> 5;
    const int rt = blockIdx.x >> 1, half = blockIdx.x & 1;
    const int i0 = rt * 128;
    const int j0 = half * 4096;
    const int row = t >> 1;              // 0..127 (w-compute row)
    const int jsub = (t & 1) * 32;       // this thread's 32 j's within chunk
    const int m0 = wid * 16;             // warp's output row block

    float* sV  = (float*)(sm + SM_V);
    float* sV5 = (float*)(sm + SM_V5);

#pragma unroll
    for (int r = 0; r < 16; r++) {
        int idx = t + r * 256;
        sV[idx]  = g_v[j0 + idx];
        sV5[idx] = g_v5[j0 + idx];
    }

    const float u  = g_u[i0 + row];
    const float u5 = g_u5[i0 + row];

    auto stage = [&](int c, int b) {
        // H tile: 64 f x 64 j fp16 = 8KB = 512 16B chunks
#pragma unroll
        for (int q = 0; q < 2; q++) {
            int c16 = t + q * 256;
            int f = c16 >> 3, col = c16 & 7;
            uint32_t off = swz((uint32_t)(f * 128 + col * 16));
            cp_async16(smb + SM_H + b * 8192 + off,
                       (const char*)&g_hT[f][j0 + c * 64] + col * 16);
        }
        // adj: 128 rows x 256B = 2048 16B chunks
#pragma unroll
        for (int q = 0; q < 8; q++) {
            int idx = t + q * 256;
            int r = idx >> 4, col = idx & 15;
            cp_async16(smb + SM_ADJ + b * (128 * ADJ_PITCH) + r * ADJ_PITCH + col * 16,
                       (const char*)(adj + (size_t)(i0 + r) * N_NODES + j0 + c * 64) + col * 16);
        }
    };

    stage(0, 0);
    cp_commit();

    float acc[8][4] = {};
    float z = 0.f;

    for (int c = 0; c < 64; c++) {
        const int b = c & 1;

        cp_wait_all();
        __syncthreads();          // staged chunk visible; prev MMA done -> P writable

        if (c + 1 < 64) {
            stage(c + 1, b ^ 1);
            cp_commit();
        }

        // ---- w-compute: this thread -> 32 j's of row `row`; store P fp16 (SW128) ----
        {
            const char* aRow = sm + SM_ADJ + b * (128 * ADJ_PITCH) + row * ADJ_PITCH + (t & 1) * 128;
            const float4* vp  = (const float4*)(sV  + c * 64 + jsub);
            const float4* v5p = (const float4*)(sV5 + c * 64 + jsub);
#pragma unroll
            for (int g = 0; g < 4; g++) {
                uint4 a0 = *(const uint4*)(aRow + g * 32);
                uint4 a1 = *(const uint4*)(aRow + g * 32 + 16);
                float4 v0 = vp[g * 2],  v1 = vp[g * 2 + 1];
                float4 q0 = v5p[g * 2], q1 = v5p[g * 2 + 1];
                float w[8];
                {
                    float t1, t2, s;
                    t1 = u * v0.x; t2 = u5 * q0.x; s = (t1 >= 1.f) ? t1 : t2; w[0] = a0.x ? s : 0.f;
                    t1 = u * v0.y; t2 = u5 * q0.y; s = (t1 >= 1.f) ? t1 : t2; w[1] = a0.y ? s : 0.f;
                    t1 = u * v0.z; t2 = u5 * q0.z; s = (t1 >= 1.f) ? t1 : t2; w[2] = a0.z ? s : 0.f;
                    t1 = u * v0.w; t2 = u5 * q0.w; s = (t1 >= 1.f) ? t1 : t2; w[3] = a0.w ? s : 0.f;
                    t1 = u * v1.x; t2 = u5 * q1.x; s = (t1 >= 1.f) ? t1 : t2; w[4] = a1.x ? s : 0.f;
                    t1 = u * v1.y; t2 = u5 * q1.y; s = (t1 >= 1.f) ? t1 : t2; w[5] = a1.y ? s : 0.f;
                    t1 = u * v1.z; t2 = u5 * q1.z; s = (t1 >= 1.f) ? t1 : t2; w[6] = a1.z ? s : 0.f;
                    t1 = u * v1.w; t2 = u5 * q1.w; s = (t1 >= 1.f) ? t1 : t2; w[7] = a1.w ? s : 0.f;
                }
                z += ((w[0] + w[1]) + (w[2] + w[3])) + ((w[4] + w[5]) + (w[6] + w[7]));

                uint32_t pk0 = cvt_f16x2(w[1], w[0]);
                uint32_t pk1 = cvt_f16x2(w[3], w[2]);
                uint32_t pk2 = cvt_f16x2(w[5], w[4]);
                uint32_t pk3 = cvt_f16x2(w[7], w[6]);
                uint32_t off = swz((uint32_t)(row * 128 + jsub * 2 + g * 16));
                *(uint4*)(sm + SM_P + off) = make_uint4(pk0, pk1, pk2, pk3);
            }
        }

        __syncthreads();          // P tile visible

        // ---- HMMA: warp computes rows m0..m0+15, all 64 cols ----
        {
            const uint32_t hbase = smb + SM_H + b * 8192;
#pragma unroll
            for (int ks = 0; ks < 4; ks++) {
                uint32_t aoff = swz((uint32_t)(((m0 + (lane & 7) + (lane & 8)) << 7) +
                                               ks * 32 + (lane & 16)));
                uint32_t af[4];
                ldsm_x4(af, smb + SM_P + aoff);
#pragma unroll
                for (int np = 0; np < 4; np++) {
                    int f = np * 16 + (lane & 7) + ((lane & 16) >> 1);
                    uint32_t boff = swz((uint32_t)((f << 7) + ks * 32 + ((lane & 8) << 1)));
                    uint32_t bf[4];
                    ldsm_x4(bf, hbase + boff);
                    mma16816(acc[2 * np],     af, bf);
                    mma16816(acc[2 * np + 1], af, bf + 2);
                }
            }
        }
    }

    // ---- epilogue ----
    float zsum = z + __shfl_xor_sync(0xffffffffu, z, 1);
    if ((t & 1) == 0) g_zp[half][i0 + row] = zsum;

    const int r0 = i0 + m0 + (lane >> 2);
    const int col = (lane & 3) * 2;
#pragma unroll
    for (int nb = 0; nb < 8; nb++) {
        *(float2*)&g_num[half][r0][nb * 8 + col]     = make_float2(acc[nb][0], acc[nb][1]);
        *(float2*)&g_num[half][r0 + 8][nb * 8 + col] = make_float2(acc[nb][2], acc[nb][3]);
    }
}

// ---------------------------------------------------------------------------
// Kernel 3: combine halves + ELU
// ---------------------------------------------------------------------------
__global__ __launch_bounds__(256) void k_combine(float* __restrict__ out) {
    int idx = blockIdx.x * 256 + threadIdx.x;   // float4 index, 131072 total
    int i = idx >> 4;
    float zinv = 1.0f / (g_zp[0][i] + g_zp[1][i]);
    float4 n0 = ((const float4*)g_num[0])[idx];
    float4 n1 = ((const float4*)g_num[1])[idx];
    float4 o;
    float v;
    v = (n0.x + n1.x) * zinv; o.x = v > 0.f ? v : expm1f(v);
    v = (n0.y + n1.y) * zinv; o.y = v > 0.f ? v : expm1f(v);
    v = (n0.z + n1.z) * zinv; o.z = v > 0.f ? v : expm1f(v);
    v = (n0.w + n1.w) * zinv; o.w = v > 0.f ? v : expm1f(v);
    ((float4*)out)[idx] = o;
}

// ---------------------------------------------------------------------------
extern "C" void kernel_launch(void* const* d_in, const int* in_sizes, int n_in,
                              void* d_out, int out_size) {
    const float* inp = (const float*)d_in[0];   // [8192,128]
    const int*   adj = (const int*)d_in[1];     // [8192,8192]
    const float* W   = (const float*)d_in[2];   // [128,64]
    const float* a   = (const float*)d_in[3];   // [128,1]
    float* out = (float*)d_out;                 // [8192,64]

    cudaFuncSetAttribute(k_proj, cudaFuncAttributeMaxDynamicSharedMemorySize, SM_PROJ);
    cudaFuncSetAttribute(k_attn, cudaFuncAttributeMaxDynamicSharedMemorySize, SM_ATTN);

    k_proj<<<N_NODES / PR, 256, SM_PROJ>>>(inp, W, a);
    k_attn<<<128, 256, SM_ATTN>>>(adj);
    k_combine<<<N_NODES * F / 4 / 256, 256>>>(out);
}